// round 6
// baseline (speedup 1.0000x reference)
#include <cuda_runtime.h>
#include <cuda_bf16.h>

// D_MODEL = 2048, QUAT_DIM = 512, B*T = 16384
// Inputs: x [B,T,2048] f32, q_left [4,512] f32, q_right [4,512] f32, gate [512] f32
// Output: [B,T,2048] f32
//
// spectral_gate broadcasts uniformly over the FFT axis => ifft(fft(x)*g).real == g*x.
// Both Hamilton products are linear in x => fused per-feature 4x4 matrix M[d].
// Single kernel: each thread builds M for its 4 features in registers, then
// streams ROWS bt-rows through it.

#define QD 512
#define NBT (4 * 4096)
#define ROWS 8
#define NBLK (NBT / ROWS)  // 2048

__device__ __forceinline__ float4 f4_fma(float4 a, float4 b, float4 c) {
    return make_float4(fmaf(a.x, b.x, c.x), fmaf(a.y, b.y, c.y),
                       fmaf(a.z, b.z, c.z), fmaf(a.w, b.w, c.w));
}
__device__ __forceinline__ float4 f4_mul(float4 a, float4 b) {
    return make_float4(a.x * b.x, a.y * b.y, a.z * b.z, a.w * b.w);
}
__device__ __forceinline__ float4 f4_scale(float4 a, float s) {
    return make_float4(a.x * s, a.y * s, a.z * s, a.w * s);
}
__device__ __forceinline__ float4 f4_sgn(float4 a, float s) {
    return s > 0.f ? a : make_float4(-a.x, -a.y, -a.z, -a.w);
}

__global__ void __launch_bounds__(128)
evolve_fused_kernel(const float* __restrict__ x,
                    const float* __restrict__ ql,
                    const float* __restrict__ qr,
                    const float* __restrict__ gate,
                    float* __restrict__ out) {
    const int d4 = threadIdx.x * 4;   // feature group (multiple of 4)
    const int bt0 = blockIdx.x * ROWS;

    // ---- Build fused 4x4 matrices for 4 features (elementwise in float4) ----
    float4 lv[4], rv[4];
#pragma unroll
    for (int i = 0; i < 4; i++) {
        lv[i] = *reinterpret_cast<const float4*>(ql + i * QD + d4);
        rv[i] = *reinterpret_cast<const float4*>(qr + i * QD + d4);
    }
    // normalize l
    {
        float4 s = make_float4(1e-8f, 1e-8f, 1e-8f, 1e-8f);
#pragma unroll
        for (int i = 0; i < 4; i++) s = f4_fma(lv[i], lv[i], s);
        float4 inv = make_float4(rsqrtf(s.x), rsqrtf(s.y), rsqrtf(s.z), rsqrtf(s.w));
#pragma unroll
        for (int i = 0; i < 4; i++) lv[i] = f4_mul(lv[i], inv);
    }
    // normalize r + conjugate (negate x,y,z)
    {
        float4 s = make_float4(1e-8f, 1e-8f, 1e-8f, 1e-8f);
#pragma unroll
        for (int i = 0; i < 4; i++) s = f4_fma(rv[i], rv[i], s);
        float4 inv = make_float4(rsqrtf(s.x), rsqrtf(s.y), rsqrtf(s.z), rsqrtf(s.w));
        rv[0] = f4_mul(rv[0], inv);
#pragma unroll
        for (int i = 1; i < 4; i++)
            rv[i] = f4_mul(rv[i], make_float4(-inv.x, -inv.y, -inv.z, -inv.w));
    }

    // Sign/index tables (constant-folded under full unroll)
    // L[r][k] = sL[r][k] * l[pL[r][k]] ; R[k][c] = sR[k][c] * r[pR[k][c]]
    const int   pP[4][4] = {{0,1,2,3},{1,0,3,2},{2,3,0,1},{3,2,1,0}};
    const float sL[4][4] = {{1,-1,-1,-1},{1,1,-1,1},{1,1,1,-1},{1,-1,1,1}};
    const float sR[4][4] = {{1,-1,-1,-1},{1,1,1,-1},{1,-1,1,1},{1,1,-1,1}};

    float4 g4 = *reinterpret_cast<const float4*>(gate + d4);

    float4 M[16];
#pragma unroll
    for (int r = 0; r < 4; r++) {
#pragma unroll
        for (int c = 0; c < 4; c++) {
            float4 acc = make_float4(0.f, 0.f, 0.f, 0.f);
#pragma unroll
            for (int k = 0; k < 4; k++) {
                float4 t = f4_mul(lv[pP[r][k]], rv[pP[k][c]]);
                acc = f4_fma(f4_sgn(t, sL[r][k] * sR[k][c]),
                             make_float4(1.f, 1.f, 1.f, 1.f), acc);
            }
            M[r * 4 + c] = f4_mul(acc, g4);
        }
    }

    // ---- Stream ROWS bt-rows through the matrices ----
    const float* xp = x + (size_t)bt0 * 2048 + d4;
    float* op = out + (size_t)bt0 * 2048 + d4;

#pragma unroll 2
    for (int rr = 0; rr < ROWS; rr++) {
        float4 in[4];
#pragma unroll
        for (int c = 0; c < 4; c++)
            in[c] = __ldcs(reinterpret_cast<const float4*>(xp + (size_t)rr * 2048 + c * QD));

#pragma unroll
        for (int r = 0; r < 4; r++) {
            float4 a = f4_mul(M[r * 4 + 0], in[0]);
            a = f4_fma(M[r * 4 + 1], in[1], a);
            a = f4_fma(M[r * 4 + 2], in[2], a);
            a = f4_fma(M[r * 4 + 3], in[3], a);
            __stcs(reinterpret_cast<float4*>(op + (size_t)rr * 2048 + r * QD), a);
        }
    }
}

extern "C" void kernel_launch(void* const* d_in, const int* in_sizes, int n_in,
                              void* d_out, int out_size) {
    const float* x    = (const float*)d_in[0];
    const float* ql   = (const float*)d_in[1];
    const float* qr   = (const float*)d_in[2];
    const float* gate = (const float*)d_in[3];
    float* out = (float*)d_out;

    evolve_fused_kernel<<<NBLK, 128>>>(x, ql, qr, gate, out);
}